// round 1
// baseline (speedup 1.0000x reference)
#include <cuda_runtime.h>

#define BATCH_N 262144
#define NBLK    1024
#define TPB     256

// scratch for deterministic two-pass reduction (no allocations allowed)
__device__ float g_partials[NBLK];

__global__ __launch_bounds__(TPB)
void diffsort_loss_kernel(const float* __restrict__ pred,
                          const float* __restrict__ labels,
                          const float* __restrict__ ema)
{
    __shared__ float s_ema[8];
    if (threadIdx.x < 8) s_ema[threadIdx.x] = ema[threadIdx.x];
    __syncthreads();

    const int row = blockIdx.x * TPB + threadIdx.x;

    // 32B/row, aligned -> two float4 loads each, fully coalesced
    const float4* p4 = reinterpret_cast<const float4*>(pred   + (size_t)row * 8);
    const float4* l4 = reinterpret_cast<const float4*>(labels + (size_t)row * 8);
    float4 pa = p4[0], pb = p4[1];
    float4 la = l4[0], lb = l4[1];

    float pr[8]  = {pa.x, pa.y, pa.z, pa.w, pb.x, pb.y, pb.z, pb.w};
    float lab[8] = {la.x, la.y, la.z, la.w, lb.x, lb.y, lb.z, lb.w};

    // rank_true[i] = descending rank of labels[i] (stable tie-break by index)
    int rt[8];
    #pragma unroll
    for (int i = 0; i < 8; i++) {
        int r = 0;
        #pragma unroll
        for (int j = 0; j < 8; j++) {
            r += (lab[j] > lab[i]) || ((lab[j] == lab[i]) && (j < i));
        }
        rt[i] = r;
    }

    // x = -(pred - rank_ema[rank_true])
    float x[8];
    #pragma unroll
    for (int i = 0; i < 8; i++) x[i] = s_ema[rt[i]] - pr[i];

    // perm matrix P in registers, init identity
    float P[8][8];
    #pragma unroll
    for (int r = 0; r < 8; r++) {
        #pragma unroll
        for (int c = 0; c < 8; c++) P[r][c] = (r == c) ? 1.0f : 0.0f;
    }

    // odd-even differentiable sorting network, 8 layers
    #pragma unroll
    for (int layer = 0; layer < 8; layer++) {
        #pragma unroll
        for (int i = (layer & 1); i < 7; i += 2) {
            float a = x[i], b = x[i + 1];
            float alpha = atanf(10.0f * (b - a)) * 0.3183098861837907f + 0.5f;
            float d = a - b;
            x[i]     = fmaf(alpha, d, b);   // alpha*a + (1-alpha)*b
            x[i + 1] = fmaf(-alpha, d, a);  // (1-alpha)*a + alpha*b
            #pragma unroll
            for (int r = 0; r < 8; r++) {
                float A = P[r][i], B = P[r][i + 1];
                float t = A - B;
                P[r][i]     = fmaf(alpha, t, B);
                P[r][i + 1] = fmaf(-alpha, t, A);
            }
        }
    }

    // loss: sum_{ij} log1p(-p) + sum_i [log(p_g) - log1p(-p_g)], g = (i, rt[i])
    // sum log1p(-p) over a column == log(prod (1-p)); prod >= pmax*(1-pmax) >> fp32 min
    float s = 0.0f;
    #pragma unroll
    for (int c = 0; c < 8; c++) {
        float prod = 1.0f;
        #pragma unroll
        for (int r = 0; r < 8; r++) prod *= (1.0f - P[r][c]);
        s += __logf(prod);
    }
    #pragma unroll
    for (int i = 0; i < 8; i++) {
        float pg = P[i][0];
        #pragma unroll
        for (int j = 1; j < 8; j++) pg = (rt[i] == j) ? P[i][j] : pg;
        s += fmaxf(__logf(pg), -100.0f) - __logf(1.0f - pg);
    }

    // deterministic block reduction
    #pragma unroll
    for (int o = 16; o > 0; o >>= 1) s += __shfl_xor_sync(0xffffffffu, s, o);
    __shared__ float ws[TPB / 32];
    if ((threadIdx.x & 31) == 0) ws[threadIdx.x >> 5] = s;
    __syncthreads();
    if (threadIdx.x == 0) {
        float bs = 0.0f;
        #pragma unroll
        for (int w = 0; w < TPB / 32; w++) bs += ws[w];
        g_partials[blockIdx.x] = bs;
    }
}

__global__ __launch_bounds__(TPB)
void reduce_final_kernel(float* __restrict__ out)
{
    const int t = threadIdx.x;
    double s = 0.0;
    #pragma unroll
    for (int k = 0; k < NBLK / TPB; k++) s += (double)g_partials[t + k * TPB];
    #pragma unroll
    for (int o = 16; o > 0; o >>= 1) s += __shfl_xor_sync(0xffffffffu, s, o);
    __shared__ double ws[TPB / 32];
    if ((t & 31) == 0) ws[t >> 5] = s;
    __syncthreads();
    if (t == 0) {
        double tot = 0.0;
        #pragma unroll
        for (int w = 0; w < TPB / 32; w++) tot += ws[w];
        out[0] = (float)(-tot / ((double)BATCH_N * 64.0));
    }
}

extern "C" void kernel_launch(void* const* d_in, const int* in_sizes, int n_in,
                              void* d_out, int out_size)
{
    const float* pred   = (const float*)d_in[0];
    const float* labels = (const float*)d_in[1];
    const float* ema    = (const float*)d_in[2];
    diffsort_loss_kernel<<<NBLK, TPB>>>(pred, labels, ema);
    reduce_final_kernel<<<1, TPB>>>((float*)d_out);
}